// round 1
// baseline (speedup 1.0000x reference)
#include <cuda_runtime.h>
#include <math.h>

// Problem dims (fixed by the dataset)
#define BB 32
#define NN 512
#define CC 128   // Cin == Cout
#define MM 64
#define TT 20
#define NH 256   // NN/2

// ---------------- scratch (device globals; no allocation) ----------------
__device__ float2 g_twf[MM][NH];        // forward twiddles  (cos, sin), theta = 2*pi*m*n/512, n<256
__device__ float2 g_twi[NH][MM];        // inverse twiddles  (alpha*cos, alpha*sin), alpha = (m==0?1:2)/512
__device__ float2 g_Wp[MM][CC][CC];     // repacked weights  [m][ci][co]
__device__ float2 g_Y[3][MM][BB][CC];   // V0=y0, V1=y0*A, V2=y0*A^2

// ---------------- K1: twiddle tables (double precision gen) ----------------
__global__ void init_tw_kernel() {
    int idx = blockIdx.x * blockDim.x + threadIdx.x;   // 64*256 = 16384
    if (idx >= MM * NH) return;
    int m = idx >> 8;          // 0..63
    int n = idx & 255;         // 0..255
    int r = (m * n) & 511;     // exact range reduction mod 512
    double s, c;
    sincospi((double)r / 256.0, &s, &c);
    g_twf[m][n] = make_float2((float)c, (float)s);
    double alpha = ((m == 0) ? 1.0 : 2.0) / 512.0;
    g_twi[n][m] = make_float2((float)(alpha * c), (float)(alpha * s));
}

// ---------------- K2: repack weights [ci][co][m][2] -> [m][ci][co] ----------------
__global__ void repack_w_kernel(const float* __restrict__ w) {
    int idx = blockIdx.x * blockDim.x + threadIdx.x;   // < 64*128*128 = 1048576
    const float2 v = reinterpret_cast<const float2*>(w)[idx];  // coalesced read
    int m  = idx & 63;
    int co = (idx >> 6) & 127;
    int ci = idx >> 13;
    g_Wp[m][ci][co] = v;
}

// ---------------- K3: forward DFT (64 modes), parity trick ----------------
// X[m,b,c] = sum_{n<256} (x[n] +- x[n+256]) * e^{-i theta_mn}   (+ for even m, - for odd)
__global__ void fdft_kernel(const float* __restrict__ x) {
    __shared__ float2 s_tw[8][NH];   // 16 KB
    int mg = blockIdx.x;             // 0..7   (8 modes per block)
    int b  = blockIdx.y;             // 0..31
    int c  = threadIdx.x;            // 0..127
    int m0 = mg * 8;

    for (int i = threadIdx.x; i < 8 * NH; i += 128) {
        int j = i >> 8; int n = i & 255;
        s_tw[j][n] = g_twf[m0 + j][n];
    }
    __syncthreads();

    float2 acc[8];
#pragma unroll
    for (int j = 0; j < 8; j++) acc[j] = make_float2(0.f, 0.f);

    const float* xb = x + (size_t)b * NN * CC + c;
#pragma unroll 2
    for (int n = 0; n < NH; n++) {
        float x0 = xb[(size_t)n * CC];
        float x1 = xb[(size_t)(n + NH) * CC];
        float xe = x0 + x1;
        float xo = x0 - x1;
#pragma unroll
        for (int j = 0; j < 8; j++) {
            float xp = (j & 1) ? xo : xe;   // m parity == j parity (m0 multiple of 8)
            float2 tw = s_tw[j][n];
            acc[j].x = fmaf(xp,  tw.x, acc[j].x);
            acc[j].y = fmaf(-xp, tw.y, acc[j].y);
        }
    }
#pragma unroll
    for (int j = 0; j < 8; j++)
        g_Y[0][m0 + j][b][c] = acc[j];
}

// ---------------- K4: per-mode complex GEMM  vout[b,co] = sum_ci vin[b,ci]*W[ci,co] ----------------
__global__ void apply_kernel(int src, int dst) {
    extern __shared__ float2 smA[];
    float2* s_w = smA;              // [128][64]  (this block's co-half)
    float2* s_y = smA + 8192;       // [32][128]
    int half = blockIdx.x;          // 0..1
    int m    = blockIdx.y;          // 0..63
    int tid  = threadIdx.x;         // 0..127

    const float2* vin = &g_Y[src][m][0][0];
    for (int i = tid; i < BB * CC; i += 128) s_y[i] = vin[i];
    const float2* wp = &g_Wp[m][0][0];
    for (int i = tid; i < 128 * 64; i += 128) {
        int ci = i >> 6, cq = i & 63;
        s_w[i] = wp[ci * CC + half * 64 + cq];
    }
    __syncthreads();

    int cg = tid & 15;      // co lane: co = cg + 16*j  (conflict-free, coalesced)
    int bg = tid >> 4;      // b group: b = bg*4 + i
    float2 acc[4][4];
#pragma unroll
    for (int i = 0; i < 4; i++)
#pragma unroll
        for (int j = 0; j < 4; j++) acc[i][j] = make_float2(0.f, 0.f);

#pragma unroll 4
    for (int ci = 0; ci < CC; ci++) {
        float2 yv[4], wv[4];
#pragma unroll
        for (int i = 0; i < 4; i++) yv[i] = s_y[(bg * 4 + i) * CC + ci];
#pragma unroll
        for (int j = 0; j < 4; j++) wv[j] = s_w[ci * 64 + cg + 16 * j];
#pragma unroll
        for (int i = 0; i < 4; i++)
#pragma unroll
            for (int j = 0; j < 4; j++) {
                acc[i][j].x = fmaf(yv[i].x, wv[j].x, acc[i][j].x);
                acc[i][j].x = fmaf(-yv[i].y, wv[j].y, acc[i][j].x);
                acc[i][j].y = fmaf(yv[i].x, wv[j].y, acc[i][j].y);
                acc[i][j].y = fmaf(yv[i].y, wv[j].x, acc[i][j].y);
            }
    }

    float2* vout = &g_Y[dst][m][0][0];
#pragma unroll
    for (int i = 0; i < 4; i++)
#pragma unroll
        for (int j = 0; j < 4; j++)
            vout[(bg * 4 + i) * CC + half * 64 + cg + 16 * j] = acc[i][j];
}

// ---------------- K5: fused inverse DFT + time assembly ----------------
// g_k[n] = sum_m alpha_m (Re(Vk) cos - Im(Vk) sin);  out[t,n] = g0 + tau*g1 + tau^2*(g2/2)
// parity accumulators give n and n+256 from one set of products.
__global__ void __launch_bounds__(256, 1) idft_out_kernel(const float* __restrict__ tg,
                                                          float* __restrict__ out) {
    extern __shared__ float smraw[];
    float2* s_tw  = (float2*)smraw;          // [128][64]   64 KB
    float2* s_V   = s_tw + 128 * 64;         // [3][64][64] 96 KB
    float*  s_tau = (float*)(s_V + 3 * 64 * 64);  // [32]

    int chalf = blockIdx.x;   // 0..1
    int nq    = blockIdx.y;   // 0..1  (base n in [nq*128, nq*128+128), pairs at +256)
    int b     = blockIdx.z;   // 0..31
    int tid   = threadIdx.x;  // 0..255

    for (int i = tid; i < 128 * 64; i += 256) {
        int n = i >> 6, m = i & 63;
        s_tw[i] = g_twi[nq * 128 + n][m];
    }
    for (int i = tid; i < 3 * 64 * 64; i += 256) {
        int k = i >> 12; int rem = i & 4095; int m = rem >> 6; int cq = rem & 63;
        s_V[i] = g_Y[k][m][b][chalf * 64 + cq];
    }
    if (tid < TT) s_tau[tid] = tg[tid] - tg[0];
    __syncthreads();

    int lane = tid & 31;
    int wrp  = tid >> 5;
    const float4* sV4 = (const float4*)s_V;      // [k][m][32] float4 (2 complex per lane)
    float2* out2 = (float2*)out;

    for (int p = 0; p < 4; p++) {
        int nb = p * 32 + wrp * 4;               // base-n of this thread's 4 rows
        float accE[4][3][2], accO[4][3][2];
#pragma unroll
        for (int i = 0; i < 4; i++)
#pragma unroll
            for (int k = 0; k < 3; k++) {
                accE[i][k][0] = 0.f; accE[i][k][1] = 0.f;
                accO[i][k][0] = 0.f; accO[i][k][1] = 0.f;
            }

#pragma unroll 2
        for (int m2 = 0; m2 < 32; m2++) {
#pragma unroll
            for (int par = 0; par < 2; par++) {
                int m = 2 * m2 + par;
                float4 v[3];
#pragma unroll
                for (int k = 0; k < 3; k++) v[k] = sV4[(k * 64 + m) * 32 + lane];
                float (*acc)[3][2] = par ? accO : accE;
#pragma unroll
                for (int i = 0; i < 4; i++) {
                    float2 tw = s_tw[(nb + i) * 64 + m];   // broadcast within warp
#pragma unroll
                    for (int k = 0; k < 3; k++) {
                        acc[i][k][0] = fmaf(tw.x,  v[k].x, acc[i][k][0]);
                        acc[i][k][0] = fmaf(-tw.y, v[k].y, acc[i][k][0]);
                        acc[i][k][1] = fmaf(tw.x,  v[k].z, acc[i][k][1]);
                        acc[i][k][1] = fmaf(-tw.y, v[k].w, acc[i][k][1]);
                    }
                }
            }
        }

        // combine parities -> (n, n+256), Horner over t, store
#pragma unroll
        for (int i = 0; i < 4; i++) {
            int nlo = nq * 128 + nb + i;
            float glo[3][2], ghi[3][2];
#pragma unroll
            for (int k = 0; k < 3; k++)
#pragma unroll
                for (int cc = 0; cc < 2; cc++) {
                    glo[k][cc] = accE[i][k][cc] + accO[i][k][cc];
                    ghi[k][cc] = accE[i][k][cc] - accO[i][k][cc];
                }
            glo[2][0] *= 0.5f; glo[2][1] *= 0.5f;
            ghi[2][0] *= 0.5f; ghi[2][1] *= 0.5f;

            size_t col = (size_t)chalf * 32 + lane;
            for (int t = 0; t < TT; t++) {
                float tau = s_tau[t];
                float2 vlo, vhi;
                vlo.x = fmaf(tau, fmaf(tau, glo[2][0], glo[1][0]), glo[0][0]);
                vlo.y = fmaf(tau, fmaf(tau, glo[2][1], glo[1][1]), glo[0][1]);
                vhi.x = fmaf(tau, fmaf(tau, ghi[2][0], ghi[1][0]), ghi[0][0]);
                vhi.y = fmaf(tau, fmaf(tau, ghi[2][1], ghi[1][1]), ghi[0][1]);
                size_t rowbase = ((size_t)(b * TT + t) * NN);
                out2[(rowbase + nlo)       * (CC / 2) + col] = vlo;
                out2[(rowbase + nlo + 256) * (CC / 2) + col] = vhi;
            }
        }
    }
}

// ---------------- launcher ----------------
extern "C" void kernel_launch(void* const* d_in, const int* in_sizes, int n_in,
                              void* d_out, int out_size) {
    const float* x  = (const float*)d_in[0];
    const float* tg = (const float*)d_in[1];
    const float* w  = (const float*)d_in[2];
    float* out = (float*)d_out;

    // dynamic smem opt-in (idempotent; host-side attribute set, not a graph op)
    static_assert(sizeof(float2) == 8, "");
    const int APPLY_SMEM = (8192 + 4096) * (int)sizeof(float2);                 // 96 KB
    const int IDFT_SMEM  = (128 * 64 + 3 * 64 * 64) * (int)sizeof(float2) + 32 * 4;  // ~160 KB
    cudaFuncSetAttribute(apply_kernel,    cudaFuncAttributeMaxDynamicSharedMemorySize, APPLY_SMEM);
    cudaFuncSetAttribute(idft_out_kernel, cudaFuncAttributeMaxDynamicSharedMemorySize, IDFT_SMEM);

    init_tw_kernel<<<64, 256>>>();
    repack_w_kernel<<<4096, 256>>>(w);
    fdft_kernel<<<dim3(8, 32), 128>>>(x);
    apply_kernel<<<dim3(2, MM), 128, APPLY_SMEM>>>(0, 1);   // V1 = V0 * A
    apply_kernel<<<dim3(2, MM), 128, APPLY_SMEM>>>(1, 2);   // V2 = V1 * A
    idft_out_kernel<<<dim3(2, 2, 32), 256, IDFT_SMEM>>>(tg, out);
}

// round 3
// speedup vs baseline: 1.0852x; 1.0852x over previous
#include <cuda_runtime.h>
#include <math.h>

// Problem dims (fixed by the dataset)
#define BB 32
#define NN 512
#define CC 128   // Cin == Cout
#define MM 64
#define TT 20
#define NH 256   // NN/2

typedef unsigned long long u64;

// ---------------- f32x2 packed helpers ----------------
__device__ __forceinline__ u64 bc2(float a) {
    u64 r; asm("mov.b64 %0,{%1,%1};" : "=l"(r) : "f"(a)); return r;
}
__device__ __forceinline__ u64 fma2(u64 a, u64 b, u64 c) {
    u64 d; asm("fma.rn.f32x2 %0,%1,%2,%3;" : "=l"(d) : "l"(a), "l"(b), "l"(c)); return d;
}
__device__ __forceinline__ u64 add2(u64 a, u64 b) {
    u64 d; asm("add.rn.f32x2 %0,%1,%2;" : "=l"(d) : "l"(a), "l"(b)); return d;
}
__device__ __forceinline__ u64 sub2(u64 a, u64 b) {
    u64 d; asm("sub.rn.f32x2 %0,%1,%2;" : "=l"(d) : "l"(a), "l"(b)); return d;
}
__device__ __forceinline__ u64 mul2(u64 a, u64 b) {
    u64 d; asm("mul.rn.f32x2 %0,%1,%2;" : "=l"(d) : "l"(a), "l"(b)); return d;
}

// ---------------- scratch (device globals; no allocation) ----------------
__device__ float2 g_twf[MM][NH];        // forward twiddles  (cos, -sin)
__device__ float2 g_twi[NH][MM];        // inverse twiddles  (alpha*cos, -alpha*sin)
__device__ float2 g_Wp[MM][CC][CC];     // repacked weights  [m][ci][co] = (re, im)
__device__ float2 g_Wp2[MM][CC][CC];    // repacked weights  [m][ci][co] = (-im, re)
__device__ float2 g_Y[3][MM][BB][CC];   // V0=y0, V1=y0*A, V2=y0*A^2

// ---------------- K1: twiddle tables (double precision gen) ----------------
__global__ void init_tw_kernel() {
    int idx = blockIdx.x * blockDim.x + threadIdx.x;   // 64*256 = 16384
    if (idx >= MM * NH) return;
    int m = idx >> 8;          // 0..63
    int n = idx & 255;         // 0..255
    int r = (m * n) & 511;     // exact range reduction mod 512
    double s, c;
    sincospi((double)r / 256.0, &s, &c);
    g_twf[m][n] = make_float2((float)c, (float)(-s));
    double alpha = ((m == 0) ? 1.0 : 2.0) / 512.0;
    g_twi[n][m] = make_float2((float)(alpha * c), (float)(-alpha * s));
}

// ---------------- K2: repack weights [ci][co][m][2] -> [m][ci][co] (smem transpose) ----------------
// grid (4 co-groups, 128 ci), block 256 threads
__global__ void repack_w_kernel(const float* __restrict__ w) {
    __shared__ float2 s[32][65];   // [co_local][m], padded
    int q  = blockIdx.x;           // co group (32 co's)
    int ci = blockIdx.y;
    int tid = threadIdx.x;
    const float2* w2 = (const float2*)w;
    for (int i = tid; i < 32 * 64; i += 256) {
        int j = i >> 6, m = i & 63;                       // j = co_local
        s[j][m] = w2[((size_t)ci * CC + q * 32 + j) * MM + m];   // coalesced over m
    }
    __syncthreads();
    for (int i = tid; i < 32 * 64; i += 256) {
        int m = i >> 5, j = i & 31;
        float2 v = s[j][m];
        g_Wp [m][ci][q * 32 + j] = v;                       // coalesced over j
        g_Wp2[m][ci][q * 32 + j] = make_float2(-v.y, v.x);
    }
}

// ---------------- K3: forward DFT (64 modes), parity trick, f32x2 ----------------
__global__ void __launch_bounds__(128) fdft_kernel(const float* __restrict__ x) {
    __shared__ float2 s_tw[8][NH];   // 16 KB
    int mg = blockIdx.x;             // 0..7   (8 modes per block)
    int b  = blockIdx.y;             // 0..31
    int c  = threadIdx.x;            // 0..127
    int m0 = mg * 8;

    for (int i = threadIdx.x; i < 8 * NH; i += 128) {
        int j = i >> 8; int n = i & 255;
        s_tw[j][n] = g_twf[m0 + j][n];
    }
    __syncthreads();

    u64 acc[8];
#pragma unroll
    for (int j = 0; j < 8; j++) acc[j] = 0ull;   // (0.f, 0.f)

    const float* xb = x + (size_t)b * NN * CC + c;
#pragma unroll 2
    for (int n = 0; n < NH; n++) {
        float x0 = xb[(size_t)n * CC];
        float x1 = xb[(size_t)(n + NH) * CC];
        u64 xe2 = bc2(x0 + x1);
        u64 xo2 = bc2(x0 - x1);
#pragma unroll
        for (int j = 0; j < 8; j++) {
            u64 tw2 = *(const u64*)&s_tw[j][n];
            acc[j] = fma2((j & 1) ? xo2 : xe2, tw2, acc[j]);  // (xp*cos, -xp*sin)
        }
    }
#pragma unroll
    for (int j = 0; j < 8; j++)
        *(u64*)&g_Y[0][m0 + j][b][c] = acc[j];
}

// ---------------- K4: per-mode complex GEMM via f32x2 dual-weight trick ----------------
// grid (4 co-quarters, 64 modes), block 128 threads, 96 KB smem -> 2 blocks/SM
__global__ void __launch_bounds__(128) apply_kernel(int src, int dst) {
    extern __shared__ u64 sm[];
    u64* s_w1 = sm;              // [128 ci][32 co]  (re, im)
    u64* s_w2 = sm + 4096;       // [128 ci][32 co]  (-im, re)
    u64* s_y  = sm + 8192;       // [32 b][128 ci]
    int q   = blockIdx.x;        // 0..3
    int m   = blockIdx.y;        // 0..63
    int tid = threadIdx.x;       // 0..127

    const u64* wp1 = (const u64*)&g_Wp [m][0][0];
    const u64* wp2 = (const u64*)&g_Wp2[m][0][0];
    for (int i = tid; i < 4096; i += 128) {
        int ci = i >> 5, cl = i & 31;
        s_w1[i] = wp1[ci * CC + q * 32 + cl];
        s_w2[i] = wp2[ci * CC + q * 32 + cl];
    }
    const u64* vin = (const u64*)&g_Y[src][m][0][0];
    for (int i = tid; i < BB * CC; i += 128) s_y[i] = vin[i];
    __syncthreads();

    int cg = tid & 15;      // co lane: co = q*32 + cg + 16*j
    int bg = tid >> 4;      // b group: b = bg*4 + i
    u64 acc[4][2];
#pragma unroll
    for (int i = 0; i < 4; i++) { acc[i][0] = 0ull; acc[i][1] = 0ull; }

#pragma unroll 4
    for (int ci = 0; ci < CC; ci++) {
        u64 yre[4], yim[4];
#pragma unroll
        for (int i = 0; i < 4; i++) {
            float2 y = *(const float2*)&s_y[(bg * 4 + i) * CC + ci];
            yre[i] = bc2(y.x); yim[i] = bc2(y.y);
        }
#pragma unroll
        for (int j = 0; j < 2; j++) {
            u64 w1 = s_w1[ci * 32 + cg + 16 * j];
            u64 w2 = s_w2[ci * 32 + cg + 16 * j];
#pragma unroll
            for (int i = 0; i < 4; i++)
                acc[i][j] = fma2(yre[i], w1, fma2(yim[i], w2, acc[i][j]));
        }
    }

    u64* vout = (u64*)&g_Y[dst][m][0][0];
#pragma unroll
    for (int i = 0; i < 4; i++)
#pragma unroll
        for (int j = 0; j < 2; j++)
            vout[(bg * 4 + i) * CC + q * 32 + cg + 16 * j] = acc[i][j];
}

// ---------------- K5: fused inverse DFT + time assembly, f32x2, 2 blocks/SM ----------------
// grid (4 cQ, 2 nHalf, 32 b) = 256 blocks, 256 threads, ~81 KB smem
__global__ void __launch_bounds__(256, 2) idft_out_kernel(const float* __restrict__ tg,
                                                          float* __restrict__ out) {
    extern __shared__ float smraw[];
    u64*   s_tw   = (u64*)smraw;                 // [64 rows][66] (padded)
    float* sRe    = (float*)(s_tw + 64 * 66);    // [3][64][32]
    float* sIm    = sRe + 3 * 64 * 32;           // [3][64][32]
    u64*   s_tau2 = (u64*)(sIm + 3 * 64 * 32);   // [20]

    int cQ = blockIdx.x;     // 0..3  (32 channels)
    int nH = blockIdx.y;     // 0..1  (128 pair-rows)
    int b  = blockIdx.z;     // 0..31
    int tid  = threadIdx.x;  // 0..255
    int lane = tid & 31, w = tid >> 5;
    int cpair = lane & 15;   // 2 adjacent channels
    int sset  = lane >> 4;

    // stage V planes (Re/Im split)
    for (int i = tid; i < 3 * 64 * 32; i += 256) {
        int k = i >> 11; int rem = i & 2047; int m = rem >> 5; int cc = rem & 31;
        float2 v = g_Y[k][m][b][cQ * 32 + cc];
        sRe[i] = v.x; sIm[i] = v.y;
    }
    if (tid < TT) s_tau2[tid] = bc2(tg[tid] - tg[0]);

    const u64 h2 = bc2(0.5f);
    unsigned col = cQ * 16 + cpair;
    int nl0 = w * 8 + sset * 4;

    for (int p = 0; p < 2; p++) {
        __syncthreads();
        for (int i = tid; i < 64 * 64; i += 256) {
            int n = i >> 6, m = i & 63;
            s_tw[n * 66 + m] = *(const u64*)&g_twi[nH * 128 + p * 64 + n][m];
        }
        __syncthreads();

        u64 acc[2][4][3];
#pragma unroll
        for (int pa = 0; pa < 2; pa++)
#pragma unroll
            for (int i = 0; i < 4; i++)
#pragma unroll
                for (int k = 0; k < 3; k++) acc[pa][i][k] = 0ull;

#pragma unroll 2
        for (int m2 = 0; m2 < 32; m2++) {
#pragma unroll
            for (int par = 0; par < 2; par++) {
                const int m = 2 * m2 + par;
                u64 re2[3], im2[3];
#pragma unroll
                for (int k = 0; k < 3; k++) {
                    re2[k] = *(const u64*)&sRe[(k * 64 + m) * 32 + 2 * cpair];
                    im2[k] = *(const u64*)&sIm[(k * 64 + m) * 32 + 2 * cpair];
                }
#pragma unroll
                for (int i = 0; i < 4; i++) {
                    float2 t = *(const float2*)&s_tw[(nl0 + i) * 66 + m];
                    u64 tx = bc2(t.x), ty = bc2(t.y);
#pragma unroll
                    for (int k = 0; k < 3; k++)
                        acc[par][i][k] = fma2(tx, re2[k], fma2(ty, im2[k], acc[par][i][k]));
                }
            }
        }

        // combine parities -> (n, n+256); Horner over t; store
        u64 glo[4][3], ghi[4][3];
#pragma unroll
        for (int i = 0; i < 4; i++) {
#pragma unroll
            for (int k = 0; k < 3; k++) {
                glo[i][k] = add2(acc[0][i][k], acc[1][i][k]);
                ghi[i][k] = sub2(acc[0][i][k], acc[1][i][k]);
            }
            glo[i][2] = mul2(glo[i][2], h2);
            ghi[i][2] = mul2(ghi[i][2], h2);
        }

        unsigned nlo = nH * 128 + p * 64 + nl0;
        u64* out2 = (u64*)out;
        unsigned baselo[4];
#pragma unroll
        for (int i = 0; i < 4; i++)
            baselo[i] = (unsigned)b * (TT * NN * 64) + (nlo + i) * 64 + col;

#pragma unroll 1
        for (int t = 0; t < TT; t++) {
            u64 tau2 = s_tau2[t];
            unsigned toff = (unsigned)t * (NN * 64);
#pragma unroll
            for (int i = 0; i < 4; i++) {
                u64 vlo = fma2(tau2, fma2(tau2, glo[i][2], glo[i][1]), glo[i][0]);
                u64 vhi = fma2(tau2, fma2(tau2, ghi[i][2], ghi[i][1]), ghi[i][0]);
                out2[baselo[i] + toff]              = vlo;
                out2[baselo[i] + toff + 256 * 64]   = vhi;
            }
        }
    }
}

// ---------------- launcher ----------------
extern "C" void kernel_launch(void* const* d_in, const int* in_sizes, int n_in,
                              void* d_out, int out_size) {
    const float* x  = (const float*)d_in[0];
    const float* tg = (const float*)d_in[1];
    const float* w  = (const float*)d_in[2];
    float* out = (float*)d_out;

    const int APPLY_SMEM = 12288 * (int)sizeof(u64);                       // 96 KB
    const int IDFT_SMEM  = 64 * 66 * 8 + 2 * 3 * 64 * 32 * 4 + 20 * 8;     // 83104 B
    (void)cudaFuncSetAttribute(apply_kernel,    cudaFuncAttributeMaxDynamicSharedMemorySize, APPLY_SMEM);
    (void)cudaFuncSetAttribute(idft_out_kernel, cudaFuncAttributeMaxDynamicSharedMemorySize, IDFT_SMEM);

    init_tw_kernel<<<64, 256>>>();
    repack_w_kernel<<<dim3(4, 128), 256>>>(w);
    fdft_kernel<<<dim3(8, 32), 128>>>(x);
    apply_kernel<<<dim3(4, MM), 128, APPLY_SMEM>>>(0, 1);   // V1 = V0 * A
    apply_kernel<<<dim3(4, MM), 128, APPLY_SMEM>>>(1, 2);   // V2 = V1 * A
    idft_out_kernel<<<dim3(4, 2, 32), 256, IDFT_SMEM>>>(tg, out);
}